// round 12
// baseline (speedup 1.0000x reference)
#include <cuda_runtime.h>
#include <cstdint>

// instant-ngp HashEncoder forward: D=3, L=16, C=2, base=16, scale=2, 2^19 hashmap.
// R11: one level per thread, TWO points per thread.
//  - level constants amortized over 2 points (less ALU per point)
//  - 8-16 gather loads in flight per thread (double MLP -> saturate L1tex)
//  - stores stay fully coalesced (two f2 stores, 128B segments per half-warp)
//  - gather pair-merge (even ix -> one float4 per corner pair) retained

#define PRIME_Y 2654435761u
#define PRIME_Z 805459861u
#define HASH_MASK 524287u  // 2^19 - 1

__device__ __forceinline__ void stg_cs_f2(float* p, float2 v) {
    asm volatile("st.global.cs.v2.f32 [%0], {%1,%2};"
                 :: "l"(p), "f"(v.x), "f"(v.y) : "memory");
}

__global__ __launch_bounds__(256, 6) void hashenc_fwd(
    const float* __restrict__ inp,   // [B, 3]
    const float* __restrict__ emb,   // [TOTAL_PARAMS * 2] scalar float view
    float* __restrict__ out,         // [B, 32]
    int B)
{
    const int gtid = blockIdx.x * blockDim.x + threadIdx.x;
    const int pair = gtid >> 4;      // point pair index
    const int l = gtid & 15;         // level index
    const int p0 = 2 * pair;
    if (p0 >= B) return;

    // ---- level constants (shared by both points) ----
    const uint32_t res = 16u << l;
    const float scale = (float)res - 1.0f;
    const bool dense = (l < 3);
    uint32_t off;
    if (dense) off = (l == 0) ? 0u : (l == 1) ? 4096u : 36864u;
    else       off = 299008u + (uint32_t)(l - 3) * 524288u;
    const uint32_t dy = dense ? res       : PRIME_Y;
    const uint32_t dz = dense ? res * res : PRIME_Z;
    const float* lvl = emb + 2u * off;

    // ---- inputs for both points (broadcast within half-warps) ----
    float X[2], Y[2], Z[2];
#pragma unroll
    for (int t = 0; t < 2; ++t) {
        const int p = p0 + t;
        X[t] = (__ldg(inp + 3 * p + 0) + 1.0f) * 0.5f;
        Y[t] = (__ldg(inp + 3 * p + 1) + 1.0f) * 0.5f;
        Z[t] = (__ldg(inp + 3 * p + 2) + 1.0f) * 0.5f;
    }

    float SX[2], SY[2];

#pragma unroll
    for (int t = 0; t < 2; ++t) {
        const float px = X[t] * scale + 0.5f;
        const float py = Y[t] * scale + 0.5f;
        const float pz = Z[t] * scale + 0.5f;

        const float gx = floorf(px);
        const float gy = floorf(py);
        const float gz = floorf(pz);

        const float tx = px - gx;
        const float ty = py - gy;
        const float tz = pz - gz;

        const uint32_t ix = (uint32_t)gx;
        const uint32_t iy = (uint32_t)gy;
        const uint32_t iz = (uint32_t)gz;

        const uint32_t cy0 = iy * dy, cy1 = cy0 + dy;
        const uint32_t cz0 = iz * dz, cz1 = cz0 + dz;

        const float wy[2] = {1.0f - ty, ty};
        const float wz[2] = {1.0f - tz, tz};

        float sx = 0.0f, sy = 0.0f;

        if ((ix & 1u) == 0u) {
            // merged: both x-corners in one 16B-aligned float4 (one line each)
#pragma unroll
            for (int c = 0; c < 4; ++c) {
                const uint32_t my = (c & 1) ? cy1 : cy0;
                const uint32_t mz = (c & 2) ? cz1 : cz0;
                const uint32_t i0 = dense ? (ix + my + mz)
                                          : ((ix ^ my ^ mz) & HASH_MASK);
                const uint32_t base = i0 & ~1u;
                const uint32_t sw = i0 & 1u;   // 0 on dense path

                const float4 g4 = __ldg((const float4*)(lvl + 2u * base));
                float2 g0, g1;
                if (sw) { g0 = make_float2(g4.z, g4.w); g1 = make_float2(g4.x, g4.y); }
                else    { g0 = make_float2(g4.x, g4.y); g1 = make_float2(g4.z, g4.w); }

                const float wyz = wy[c & 1] * wz[(c >> 1) & 1];
                const float w1 = tx * wyz;
                const float w0 = wyz - w1;
                sx = fmaf(w0, g0.x, fmaf(w1, g1.x, sx));
                sy = fmaf(w0, g0.y, fmaf(w1, g1.y, sy));
            }
        } else {
            const uint32_t ix1 = ix + 1u;
#pragma unroll
            for (int c = 0; c < 4; ++c) {
                const uint32_t my = (c & 1) ? cy1 : cy0;
                const uint32_t mz = (c & 2) ? cz1 : cz0;
                uint32_t i0, i1;
                if (dense) {
                    i0 = ix + my + mz;
                    i1 = i0 + 1u;
                } else {
                    const uint32_t m = my ^ mz;
                    i0 = (ix  ^ m) & HASH_MASK;
                    i1 = (ix1 ^ m) & HASH_MASK;
                }
                const float2 g0 = __ldg((const float2*)(lvl + 2u * i0));
                const float2 g1 = __ldg((const float2*)(lvl + 2u * i1));

                const float wyz = wy[c & 1] * wz[(c >> 1) & 1];
                const float w1 = tx * wyz;
                const float w0 = wyz - w1;
                sx = fmaf(w0, g0.x, fmaf(w1, g1.x, sx));
                sy = fmaf(w0, g0.y, fmaf(w1, g1.y, sy));
            }
        }

        SX[t] = sx;
        SY[t] = sy;
    }

    // two fully-coalesced 8B stores: lanes 0-15 of each half-warp cover one
    // 128B output row per store
    float2* o2 = (float2*)out;
    stg_cs_f2((float*)&o2[(size_t)p0 * 16 + l],        make_float2(SX[0], SY[0]));
    if (p0 + 1 < B)
        stg_cs_f2((float*)&o2[(size_t)(p0 + 1) * 16 + l], make_float2(SX[1], SY[1]));
}

extern "C" void kernel_launch(void* const* d_in, const int* in_sizes, int n_in,
                              void* d_out, int out_size)
{
    const float* p0 = (const float*)d_in[0];
    const float* p1 = (const float*)d_in[1];
    const float* inp;
    const float* emb;
    int B;
    if (in_sizes[0] < in_sizes[1]) {
        inp = p0; emb = p1; B = in_sizes[0] / 3;
    } else {
        inp = p1; emb = p0; B = in_sizes[1] / 3;
    }
    const int threads = 256;
    const long long npairs = ((long long)B + 1) / 2;
    const long long total = npairs * 16;
    const int blocks = (int)((total + threads - 1) / threads);
    hashenc_fwd<<<blocks, threads>>>(inp, emb, (float*)d_out, B);
}